// round 16
// baseline (speedup 1.0000x reference)
#include <cuda_runtime.h>
#include <cstdint>

// USR_EMB: out[row] = emb[searchsorted(userlist, x[row])], 64 f32/row.
// Converged at the LTS roofline (~420MB L2 crossings @ ~11TB/s = 98% of the
// HW-measured cap). R16 = last sm_103a-specific lever: 256-bit memory ops
// (ld/st.global.v8.f32, Blackwell-only) — 8 lanes x 32B per row instead of
// 16 x 16B, halving LDG/STG instruction count and L1tex wavefront-dispatch
// work per byte. Index phase unchanged: O(1) structural proof that
// userlist == arange(-1,N-1) (sorted + distinct + endpoints) => idx = u+1,
// with per-row binary-search fallback for full generality.

static constexpr int EMB = 64;
static constexpr int ROWB = EMB * 4;   // 256 bytes per row
static constexpr int RPW  = 16;        // rows per warp

// 256-bit vector load (global, .cg: cache at L2, no L1 allocation).
#define LDG256_CG(v, ptr)                                              \
    asm volatile("ld.global.cg.v8.f32 {%0,%1,%2,%3,%4,%5,%6,%7}, [%8];" \
        : "=f"((v)[0]), "=f"((v)[1]), "=f"((v)[2]), "=f"((v)[3]),       \
          "=f"((v)[4]), "=f"((v)[5]), "=f"((v)[6]), "=f"((v)[7])        \
        : "l"(ptr))

// 256-bit vector store (global, .cs: streaming / evict-first).
#define STG256_CS(ptr, v)                                              \
    asm volatile("st.global.cs.v8.f32 [%0], {%1,%2,%3,%4,%5,%6,%7,%8};" \
        :: "l"(ptr),                                                    \
           "f"((v)[0]), "f"((v)[1]), "f"((v)[2]), "f"((v)[3]),          \
           "f"((v)[4]), "f"((v)[5]), "f"((v)[6]), "f"((v)[7])           \
        : "memory")

__global__ void __launch_bounds__(256) usr_emb_kernel(
    const int* __restrict__ x,
    const int* __restrict__ userlist,
    const float* __restrict__ emb,       // [emb_rows][64] f32
    float* __restrict__ out,             // [n_rows][64] f32
    int n_rows, int n_userlist, int emb_rows)
{
    int warpId = (blockIdx.x * blockDim.x + threadIdx.x) >> 5;
    int lane   = threadIdx.x & 31;
    int sub    = lane >> 3;              // row-within-quad (0..3)
    int chunk  = lane & 7;               // 32B chunk within row (0..7)
    int wrow0  = warpId * RPW;
    if (wrow0 >= n_rows) return;

    bool full = (wrow0 + RPW) <= n_rows;

    // ---- O(1) structural proof of the fast path (warp-uniform loads) ----
    // Sorted + all-distinct (problem semantics) + endpoints -1 and N-2
    // => userlist == arange(-1, N-1) => searchsorted(u) == clamp(u+1).
    bool fastOK = (__ldg(&userlist[0]) == -1) &&
                  (__ldg(&userlist[n_userlist - 1]) == n_userlist - 2);

    // ---- Cooperative index computation: lanes 0-15, one row each ----
    int myIdx = 0;
    if (lane < RPW) {
        int r = wrow0 + lane;
        int u = (full || r < n_rows) ? __ldcs(&x[r]) : 0;  // coalesced 64B
        int i;
        if (fastOK) {
            i = u + 1;                               // proven exact
        } else {
            // Generic lower_bound: first i with userlist[i] >= u.
            int lo = 0, hi = n_userlist;
            while (lo < hi) {
                int mid = (lo + hi) >> 1;
                if (__ldg(&userlist[mid]) < u) lo = mid + 1; else hi = mid;
            }
            i = lo;
        }
        // Clamp like jax's OOB-gather clamping.
        if (i >= emb_rows) i = emb_rows - 1;
        if (i < 0) i = 0;
        myIdx = i;
    }

    // Thread's 4 rows: batch b -> warp-row b*4 + sub.
    int idx[4];
#pragma unroll
    for (int b = 0; b < 4; b++)
        idx[b] = __shfl_sync(0xffffffffu, myIdx, b * 4 + sub);

    // Byte offsets (32B-aligned: rows are 256B, chunks 32B).
    const char* embB = (const char*)emb;
    char*       outB = (char*)out;
    size_t cOff = (size_t)chunk * 32;

    if (full) {
        // ---- 4 independent 256-bit gathers in one burst (L2-hit, .cg) ----
        float v[4][8];
#pragma unroll
        for (int b = 0; b < 4; b++)
            LDG256_CG(v[b], embB + (size_t)idx[b] * ROWB + cOff);

        // ---- 4 unpredicated 256-bit streaming stores ----
        // Warp store b covers rows wrow0+b*4 .. +3 = 1KB contiguous.
#pragma unroll
        for (int b = 0; b < 4; b++) {
            size_t r = (size_t)(wrow0 + b * 4 + sub);
            STG256_CS(outB + r * ROWB + cOff, v[b]);
        }
    } else {
        // Guarded tail path (generic shapes).
#pragma unroll
        for (int b = 0; b < 4; b++) {
            int r = wrow0 + b * 4 + sub;
            if (r < n_rows) {
                float v[8];
                LDG256_CG(v, embB + (size_t)idx[b] * ROWB + cOff);
                STG256_CS(outB + (size_t)r * ROWB + cOff, v);
            }
        }
    }
}

extern "C" void kernel_launch(void* const* d_in, const int* in_sizes, int n_in,
                              void* d_out, int out_size)
{
    const int*   x        = (const int*)d_in[0];    // [B*H] int32
    const int*   userlist = (const int*)d_in[1];    // [N+1] int32
    const float* emb      = (const float*)d_in[2];  // [(N+1)*64] f32

    int n_rows     = in_sizes[0];          // 819200
    int n_userlist = in_sizes[1];          // 100001
    int emb_rows   = in_sizes[2] / EMB;    // 100001

    int n_warps = (n_rows + RPW - 1) / RPW;          // 51200
    long long total_threads = (long long)n_warps * 32;
    int block = 256;
    int grid  = (int)((total_threads + block - 1) / block);  // 6400

    usr_emb_kernel<<<grid, block>>>(x, userlist, emb,
                                    (float*)d_out, n_rows, n_userlist, emb_rows);
}